// round 1
// baseline (speedup 1.0000x reference)
#include <cuda_runtime.h>
#include <math.h>

#define BB 4096
#define DD 128

// ---------------- scratch (device globals; no allocation allowed) ----------------
__device__ float g_x[BB*DD];
__device__ float g_y[BB*DD];
__device__ float g_qkv[BB*3*DD];
__device__ float g_attn[BB*DD];
__device__ float g_h[BB*4*DD];
__device__ float g_ca[10*DD];

// ---------------- embed: x = coords@ce_w.T + ce_b + PE ----------------
__global__ void k_embed(const float* __restrict__ coords, const float* __restrict__ ce_w,
                        const float* __restrict__ ce_b) {
    int i = blockIdx.x, d = threadIdx.x;
    float c0 = coords[2*i], c1 = coords[2*i+1];
    int j = d >> 1;
    // div = 10000^(2j/128) = exp(ln(10000) * j/64)
    float dv = expf(9.210340371976184f * (float)j * (1.0f/64.0f));
    float pe = (d & 1) ? cosf(c1 / dv) : sinf(c0 / dv);
    g_x[i*DD + d] = c0*ce_w[2*d] + c1*ce_w[2*d+1] + ce_b[d] + pe;
}

// ---------------- generic fp32 GEMM: C = act(A[M,K] @ W[N,K]^T + bias) (+R) ----------------
// ACT: 0 = none, 1 = exact gelu
template<int ACT>
__global__ __launch_bounds__(256) void k_gemm(const float* __restrict__ A, const float* __restrict__ W,
                                              const float* __restrict__ bias, const float* __restrict__ R,
                                              float* __restrict__ C, int N, int K) {
    __shared__ float As[16][68];
    __shared__ float Ws[16][68];
    int tid = threadIdx.x;
    int ty = tid >> 4, tx = tid & 15;
    int m0 = blockIdx.y * 64, n0 = blockIdx.x * 64;
    int lr = tid >> 2;            // 0..63
    int lk = (tid & 3) << 2;      // 0,4,8,12
    float acc[4][4] = {};
    for (int k0 = 0; k0 < K; k0 += 16) {
        float4 av = *(const float4*)(A + (size_t)(m0 + lr)*K + k0 + lk);
        float4 wv = *(const float4*)(W + (size_t)(n0 + lr)*K + k0 + lk);
        __syncthreads();
        As[lk+0][lr] = av.x; As[lk+1][lr] = av.y; As[lk+2][lr] = av.z; As[lk+3][lr] = av.w;
        Ws[lk+0][lr] = wv.x; Ws[lk+1][lr] = wv.y; Ws[lk+2][lr] = wv.z; Ws[lk+3][lr] = wv.w;
        __syncthreads();
        #pragma unroll
        for (int k = 0; k < 16; k++) {
            float4 a0 = *(const float4*)&As[k][ty*4];
            float4 w0 = *(const float4*)&Ws[k][tx*4];
            float a[4] = {a0.x, a0.y, a0.z, a0.w};
            float w[4] = {w0.x, w0.y, w0.z, w0.w};
            #pragma unroll
            for (int r = 0; r < 4; r++)
                #pragma unroll
                for (int c = 0; c < 4; c++) acc[r][c] += a[r]*w[c];
        }
    }
    #pragma unroll
    for (int r = 0; r < 4; r++) {
        int row = m0 + ty*4 + r;
        float4 v;
        float* vp = (float*)&v;
        #pragma unroll
        for (int c = 0; c < 4; c++) {
            float val = acc[r][c] + bias[n0 + tx*4 + c];
            if (ACT == 1) val = 0.5f*val*(1.0f + erff(val*0.7071067811865475f));
            vp[c] = val;
        }
        if (R) {
            float4 rv = *(const float4*)(R + (size_t)row*N + n0 + tx*4);
            v.x += rv.x; v.y += rv.y; v.z += rv.z; v.w += rv.w;
        }
        *(float4*)(C + (size_t)row*N + n0 + tx*4) = v;
    }
}

// ---------------- flash attention: 1 CTA = 128 queries x 1 head ----------------
__global__ __launch_bounds__(256, 1) void k_attn() {
    extern __shared__ float sm[];
    float* Qs = sm;                    // [32][128] e-major
    float* Ks = sm + 32*128;           // [32][128] e-major
    float* Vs = Ks + 32*128;           // [128][36] row-major (padded)
    float* Ps = Vs + 128*36;           // [128][132] (padded)

    int h  = blockIdx.y;
    int q0 = blockIdx.x * 128;
    int tid  = threadIdx.x;
    int ty   = tid >> 4, tx = tid & 15;
    int lrow = tid >> 1, half = tid & 1;

    // load Q tile transposed
    {
        const float* gq = g_qkv + (size_t)(q0 + lrow)*384 + h*32 + half*16;
        #pragma unroll
        for (int u = 0; u < 4; u++) {
            float4 qv = *(const float4*)(gq + u*4);
            int e = half*16 + u*4;
            Qs[(e+0)*128 + lrow] = qv.x;
            Qs[(e+1)*128 + lrow] = qv.y;
            Qs[(e+2)*128 + lrow] = qv.z;
            Qs[(e+3)*128 + lrow] = qv.w;
        }
    }

    float m[8], l[8], o[8][2];
    #pragma unroll
    for (int r = 0; r < 8; r++) { m[r] = -1e30f; l[r] = 0.f; o[r][0] = 0.f; o[r][1] = 0.f; }

    for (int kv0 = 0; kv0 < BB; kv0 += 128) {
        // load K (transposed) and V (row-major)
        {
            const float* gk = g_qkv + (size_t)(kv0 + lrow)*384 + 128 + h*32 + half*16;
            const float* gv = g_qkv + (size_t)(kv0 + lrow)*384 + 256 + h*32 + half*16;
            #pragma unroll
            for (int u = 0; u < 4; u++) {
                float4 kvv = *(const float4*)(gk + u*4);
                int e = half*16 + u*4;
                Ks[(e+0)*128 + lrow] = kvv.x;
                Ks[(e+1)*128 + lrow] = kvv.y;
                Ks[(e+2)*128 + lrow] = kvv.z;
                Ks[(e+3)*128 + lrow] = kvv.w;
                float4 vv = *(const float4*)(gv + u*4);
                *(float4*)&Vs[lrow*36 + half*16 + u*4] = vv;
            }
        }
        __syncthreads();

        // S = Q K^T (128x128), 8x8 micro-tile per thread
        float s[8][8];
        #pragma unroll
        for (int r = 0; r < 8; r++)
            #pragma unroll
            for (int c = 0; c < 8; c++) s[r][c] = 0.f;
        #pragma unroll 4
        for (int e = 0; e < 32; e++) {
            float4 qa = *(const float4*)&Qs[e*128 + ty*8];
            float4 qb = *(const float4*)&Qs[e*128 + ty*8 + 4];
            float4 ka = *(const float4*)&Ks[e*128 + tx*8];
            float4 kb = *(const float4*)&Ks[e*128 + tx*8 + 4];
            float qf[8] = {qa.x, qa.y, qa.z, qa.w, qb.x, qb.y, qb.z, qb.w};
            float kf[8] = {ka.x, ka.y, ka.z, ka.w, kb.x, kb.y, kb.z, kb.w};
            #pragma unroll
            for (int r = 0; r < 8; r++)
                #pragma unroll
                for (int c = 0; c < 8; c++) s[r][c] += qf[r]*kf[c];
        }

        // online softmax (row stats across the 16 tx lanes, contiguous 16-lane groups)
        #pragma unroll
        for (int r = 0; r < 8; r++) {
            float mx = -1e30f;
            #pragma unroll
            for (int c = 0; c < 8; c++) { s[r][c] *= 0.17677669529663688f; mx = fmaxf(mx, s[r][c]); }
            #pragma unroll
            for (int off = 8; off > 0; off >>= 1) mx = fmaxf(mx, __shfl_xor_sync(0xffffffffu, mx, off, 16));
            float mi = fmaxf(m[r], mx);
            float alpha = __expf(m[r] - mi);
            float rs = 0.f;
            #pragma unroll
            for (int c = 0; c < 8; c++) {
                float p = __expf(s[r][c] - mi);
                Ps[(ty*8 + r)*132 + tx*8 + c] = p;
                rs += p;
            }
            #pragma unroll
            for (int off = 8; off > 0; off >>= 1) rs += __shfl_xor_sync(0xffffffffu, rs, off, 16);
            l[r] = l[r]*alpha + rs;
            m[r] = mi;
            o[r][0] *= alpha; o[r][1] *= alpha;
        }
        __syncthreads();

        // O += P V  (each thread: 8 rows x 2 output dims)
        #pragma unroll 4
        for (int k = 0; k < 128; k++) {
            float2 v2 = *(const float2*)&Vs[k*36 + tx*2];
            #pragma unroll
            for (int r = 0; r < 8; r++) {
                float p = Ps[(ty*8 + r)*132 + k];
                o[r][0] += p*v2.x;
                o[r][1] += p*v2.y;
            }
        }
        __syncthreads();
    }

    #pragma unroll
    for (int r = 0; r < 8; r++) {
        float inv = 1.0f / l[r];
        int row = q0 + ty*8 + r;
        g_attn[(size_t)row*128 + h*32 + tx*2 + 0] = o[r][0]*inv;
        g_attn[(size_t)row*128 + h*32 + tx*2 + 1] = o[r][1]*inv;
    }
}

// ---------------- layernorm (optional per-class add via labels) ----------------
__global__ void k_ln(const float* __restrict__ y, const float* __restrict__ g, const float* __restrict__ bb,
                     const float* __restrict__ catab, const int* __restrict__ labels,
                     float* __restrict__ out) {
    int i = blockIdx.x, d = threadIdx.x;
    float v = y[i*DD + d];
    if (catab) v += catab[labels[i]*DD + d];
    float s = v, s2 = v*v;
    #pragma unroll
    for (int off = 16; off > 0; off >>= 1) {
        s  += __shfl_xor_sync(0xffffffffu, s,  off);
        s2 += __shfl_xor_sync(0xffffffffu, s2, off);
    }
    __shared__ float sm1[4], sm2[4];
    int w = d >> 5, lane = d & 31;
    if (lane == 0) { sm1[w] = s; sm2[w] = s2; }
    __syncthreads();
    s  = sm1[0] + sm1[1] + sm1[2] + sm1[3];
    s2 = sm2[0] + sm2[1] + sm2[2] + sm2[3];
    float mean = s * (1.0f/128.0f);
    float var  = s2 * (1.0f/128.0f) - mean*mean;
    out[i*DD + d] = (v - mean)*rsqrtf(var + 1e-5f)*g[d] + bb[d];
}

// ---------------- per-class cross-attn table (10 classes only!) ----------------
__global__ void k_ca(const float* __restrict__ emb, const float* __restrict__ wv, const float* __restrict__ bv,
                     const float* __restrict__ wo, const float* __restrict__ bo) {
    __shared__ float e[128], t[128];
    int c = blockIdx.x, j = threadIdx.x;
    e[j] = emb[c*128 + j];
    __syncthreads();
    float s = bv[j];
    #pragma unroll 8
    for (int d0 = 0; d0 < 128; d0++) s += e[d0]*wv[j*128 + d0];
    t[j] = s;
    __syncthreads();
    float s2 = bo[j];
    #pragma unroll 8
    for (int d0 = 0; d0 < 128; d0++) s2 += t[d0]*wo[j*128 + d0];
    g_ca[c*128 + j] = s2;
}

// ---------------- final: sigmoid(x @ fin_w.T + fin_b), warp per row ----------------
__global__ void k_final(const float* __restrict__ x, const float* __restrict__ w, const float* __restrict__ b,
                        float* __restrict__ out) {
    int gt = blockIdx.x*blockDim.x + threadIdx.x;
    int row = gt >> 5, lane = gt & 31;
    if (row >= BB) return;
    float s = 0.f;
    #pragma unroll
    for (int j = 0; j < 4; j++) s += x[(size_t)row*128 + lane + j*32] * w[lane + j*32];
    #pragma unroll
    for (int off = 16; off > 0; off >>= 1) s += __shfl_xor_sync(0xffffffffu, s, off);
    if (lane == 0) out[row] = 1.0f/(1.0f + expf(-(s + b[0])));
}

// ---------------- launch ----------------
extern "C" void kernel_launch(void* const* d_in, const int* in_sizes, int n_in,
                              void* d_out, int out_size) {
    const float* coords   = (const float*)d_in[0];
    const int*   labels   = (const int*)  d_in[1];
    const float* ce_w     = (const float*)d_in[2];
    const float* ce_b     = (const float*)d_in[3];
    const float* emb      = (const float*)d_in[4];
    const float* sa_in_w  = (const float*)d_in[5];
    const float* sa_in_b  = (const float*)d_in[6];
    const float* sa_out_w = (const float*)d_in[7];
    const float* sa_out_b = (const float*)d_in[8];
    const float* n1_g     = (const float*)d_in[9];
    const float* n1_b     = (const float*)d_in[10];
    const float* m1_w1    = (const float*)d_in[11];
    const float* m1_b1    = (const float*)d_in[12];
    const float* m1_w2    = (const float*)d_in[13];
    const float* m1_b2    = (const float*)d_in[14];
    const float* n2_g     = (const float*)d_in[15];
    const float* n2_b     = (const float*)d_in[16];
    const float* ca_in_w  = (const float*)d_in[17];
    const float* ca_in_b  = (const float*)d_in[18];
    const float* ca_out_w = (const float*)d_in[19];
    const float* ca_out_b = (const float*)d_in[20];
    const float* n3_g     = (const float*)d_in[21];
    const float* n3_b     = (const float*)d_in[22];
    const float* m2_w1    = (const float*)d_in[23];
    const float* m2_b1    = (const float*)d_in[24];
    const float* m2_w2    = (const float*)d_in[25];
    const float* m2_b2    = (const float*)d_in[26];
    const float* n4_g     = (const float*)d_in[27];
    const float* n4_b     = (const float*)d_in[28];
    const float* fin_w    = (const float*)d_in[29];
    const float* fin_b    = (const float*)d_in[30];
    float* out = (float*)d_out;

    float *px, *py, *pqkv, *pattn, *ph, *pca;
    cudaGetSymbolAddress((void**)&px,    g_x);
    cudaGetSymbolAddress((void**)&py,    g_y);
    cudaGetSymbolAddress((void**)&pqkv,  g_qkv);
    cudaGetSymbolAddress((void**)&pattn, g_attn);
    cudaGetSymbolAddress((void**)&ph,    g_h);
    cudaGetSymbolAddress((void**)&pca,   g_ca);

    const int ATTN_SMEM = (32*128 + 32*128 + 128*36 + 128*132) * 4;  // 118784 B
    cudaFuncSetAttribute(k_attn, cudaFuncAttributeMaxDynamicSharedMemorySize, ATTN_SMEM);

    // x = embed(coords)
    k_embed<<<BB, 128>>>(coords, ce_w, ce_b);
    // qkv = x @ sa_in_w^T + b
    k_gemm<0><<<dim3(6, 64), 256>>>(px, sa_in_w, sa_in_b, nullptr, pqkv, 384, 128);
    // flash attention
    k_attn<<<dim3(32, 4), 256, ATTN_SMEM>>>();
    // y = x + attn @ sa_out_w^T + b ; x = ln1(y)
    k_gemm<0><<<dim3(2, 64), 256>>>(pattn, sa_out_w, sa_out_b, px, py, 128, 128);
    k_ln<<<BB, 128>>>(py, n1_g, n1_b, nullptr, nullptr, px);
    // mlp1: h = gelu(x@w1^T+b1); y = x + h@w2^T+b2; x = ln2(y)
    k_gemm<1><<<dim3(8, 64), 256>>>(px, m1_w1, m1_b1, nullptr, ph, 512, 128);
    k_gemm<0><<<dim3(2, 64), 256>>>(ph, m1_w2, m1_b2, px, py, 128, 512);
    k_ln<<<BB, 128>>>(py, n2_g, n2_b, nullptr, nullptr, px);
    // per-class ca table, then y = ln3(x + ca[label])
    k_ca<<<10, 128>>>(emb, ca_in_w + 2*DD*DD, ca_in_b + 2*DD, ca_out_w, ca_out_b);
    k_ln<<<BB, 128>>>(px, n3_g, n3_b, pca, labels, py);
    // mlp2: h = gelu(y@w1^T+b1); x = y + h@w2^T+b2; y = ln4(x)
    k_gemm<1><<<dim3(8, 64), 256>>>(py, m2_w1, m2_b1, nullptr, ph, 512, 128);
    k_gemm<0><<<dim3(2, 64), 256>>>(ph, m2_w2, m2_b2, py, px, 128, 512);
    k_ln<<<BB, 128>>>(px, n4_g, n4_b, nullptr, nullptr, py);
    // out = sigmoid(y @ fin_w^T + fin_b)
    k_final<<<512, 256>>>(py, fin_w, fin_b, out);
}

// round 2
// speedup vs baseline: 1.0927x; 1.0927x over previous
#include <cuda_runtime.h>
#include <math.h>

#define BB 4096
#define DD 128

typedef unsigned long long u64;

// ---- packed fp32x2 helpers (Blackwell FFMA2 path; 2x fp32 throughput) ----
__device__ __forceinline__ u64 dup2(float a) {
    u64 r; asm("mov.b64 %0,{%1,%1};" : "=l"(r) : "f"(a)); return r;
}
__device__ __forceinline__ u64 ffma2(u64 a, u64 b, u64 c) {
    u64 d; asm("fma.rn.f32x2 %0,%1,%2,%3;" : "=l"(d) : "l"(a), "l"(b), "l"(c)); return d;
}
__device__ __forceinline__ u64 fmul2(u64 a, u64 b) {
    u64 d; asm("mul.rn.f32x2 %0,%1,%2;" : "=l"(d) : "l"(a), "l"(b)); return d;
}
__device__ __forceinline__ float2 unpk(u64 v) {
    float2 f; asm("mov.b64 {%0,%1},%2;" : "=f"(f.x), "=f"(f.y) : "l"(v)); return f;
}

// ---------------- scratch ----------------
__device__ float g_x[BB*DD];
__device__ float g_y[BB*DD];
__device__ float g_qkv[BB*3*DD];
__device__ float g_attn[BB*DD];
__device__ float g_h[BB*4*DD];
__device__ float g_ca[10*DD];

// ---------------- embed ----------------
__global__ void k_embed(const float* __restrict__ coords, const float* __restrict__ ce_w,
                        const float* __restrict__ ce_b) {
    int i = blockIdx.x, d = threadIdx.x;
    float c0 = coords[2*i], c1 = coords[2*i+1];
    int j = d >> 1;
    float dv = expf(9.210340371976184f * (float)j * (1.0f/64.0f));
    float pe = (d & 1) ? cosf(c1 / dv) : sinf(c0 / dv);
    g_x[i*DD + d] = c0*ce_w[2*d] + c1*ce_w[2*d+1] + ce_b[d] + pe;
}

// ---------------- GEMM: C = act(A[M,K]@W[N,K]^T + b) (+R) ----------------
// 32x64 tile, 128 threads, double-buffered, f32x2 micro-kernel
template<int ACT>
__global__ __launch_bounds__(128) void k_gemm(const float* __restrict__ A, const float* __restrict__ W,
                                              const float* __restrict__ bias, const float* __restrict__ R,
                                              float* __restrict__ C, int N, int K) {
    __shared__ float As[2][16][36];
    __shared__ float Ws[2][16][68];
    int tid = threadIdx.x;
    int ty = tid >> 4, tx = tid & 15;          // micro: 4 rows x 4 cols
    int m0 = blockIdx.y * 32, n0 = blockIdx.x * 64;
    int ar = tid >> 2, ak = (tid & 3) << 2;    // A: 32 rows x 16 k
    int wr = tid >> 1, wk = (tid & 1) << 3;    // W: 64 rows x 16 k
    const float* Ap = A + (size_t)(m0 + ar)*K + ak;
    const float* Wp = W + (size_t)(n0 + wr)*K + wk;
    int nt = K >> 4;

    // prologue: fill buffer 0
    {
        float4 av = *(const float4*)Ap;
        float4 w0 = *(const float4*)Wp;
        float4 w1 = *(const float4*)(Wp + 4);
        As[0][ak+0][ar]=av.x; As[0][ak+1][ar]=av.y; As[0][ak+2][ar]=av.z; As[0][ak+3][ar]=av.w;
        Ws[0][wk+0][wr]=w0.x; Ws[0][wk+1][wr]=w0.y; Ws[0][wk+2][wr]=w0.z; Ws[0][wk+3][wr]=w0.w;
        Ws[0][wk+4][wr]=w1.x; Ws[0][wk+5][wr]=w1.y; Ws[0][wk+6][wr]=w1.z; Ws[0][wk+7][wr]=w1.w;
    }
    __syncthreads();

    u64 acc[4][2];
    #pragma unroll
    for (int r = 0; r < 4; r++) { acc[r][0] = 0ULL; acc[r][1] = 0ULL; }

    for (int t = 0; t < nt; t++) {
        float4 nav, nw0, nw1;
        if (t + 1 < nt) {
            nav = *(const float4*)(Ap + (t+1)*16);
            nw0 = *(const float4*)(Wp + (t+1)*16);
            nw1 = *(const float4*)(Wp + (t+1)*16 + 4);
        }
        int b = t & 1;
        #pragma unroll
        for (int k = 0; k < 16; k++) {
            float4 a4 = *(const float4*)&As[b][k][ty*4];
            ulonglong2 w2 = *(const ulonglong2*)&Ws[b][k][tx*4];
            u64 d0 = dup2(a4.x), d1 = dup2(a4.y), d2 = dup2(a4.z), d3 = dup2(a4.w);
            acc[0][0] = ffma2(d0, w2.x, acc[0][0]); acc[0][1] = ffma2(d0, w2.y, acc[0][1]);
            acc[1][0] = ffma2(d1, w2.x, acc[1][0]); acc[1][1] = ffma2(d1, w2.y, acc[1][1]);
            acc[2][0] = ffma2(d2, w2.x, acc[2][0]); acc[2][1] = ffma2(d2, w2.y, acc[2][1]);
            acc[3][0] = ffma2(d3, w2.x, acc[3][0]); acc[3][1] = ffma2(d3, w2.y, acc[3][1]);
        }
        if (t + 1 < nt) {
            int nb = b ^ 1;
            As[nb][ak+0][ar]=nav.x; As[nb][ak+1][ar]=nav.y; As[nb][ak+2][ar]=nav.z; As[nb][ak+3][ar]=nav.w;
            Ws[nb][wk+0][wr]=nw0.x; Ws[nb][wk+1][wr]=nw0.y; Ws[nb][wk+2][wr]=nw0.z; Ws[nb][wk+3][wr]=nw0.w;
            Ws[nb][wk+4][wr]=nw1.x; Ws[nb][wk+5][wr]=nw1.y; Ws[nb][wk+6][wr]=nw1.z; Ws[nb][wk+7][wr]=nw1.w;
        }
        __syncthreads();
    }

    #pragma unroll
    for (int r = 0; r < 4; r++) {
        int row = m0 + ty*4 + r;
        float2 f0 = unpk(acc[r][0]);
        float2 f1 = unpk(acc[r][1]);
        float vals[4] = {f0.x, f0.y, f1.x, f1.y};
        float4 v; float* vp = (float*)&v;
        #pragma unroll
        for (int c = 0; c < 4; c++) {
            float val = vals[c] + bias[n0 + tx*4 + c];
            if (ACT == 1) val = 0.5f*val*(1.0f + erff(val*0.7071067811865475f));
            vp[c] = val;
        }
        if (R) {
            float4 rv = *(const float4*)(R + (size_t)row*N + n0 + tx*4);
            v.x += rv.x; v.y += rv.y; v.z += rv.z; v.w += rv.w;
        }
        *(float4*)(C + (size_t)row*N + n0 + tx*4) = v;
    }
}

// ---------------- flash attention: 1 CTA = 128 queries x 1 head ----------------
// S: 8x8 micro-tile with column-paired f32x2; PV: 4 rows (stride 32) x 4 dims, f32x2.
// alpha/l passed between the two thread mappings via spare Ps columns 128/129.
__global__ __launch_bounds__(256, 1) void k_attn() {
    extern __shared__ float sm[];
    float* Qs = sm;                    // [32][128] e-major
    float* Ks = sm + 32*128;           // [32][128] e-major
    float* Vs = Ks + 32*128;           // [128][36]
    float* Ps = Vs + 128*36;           // [128][132]; col 128 = alpha, col 129 = l

    int h  = blockIdx.y;
    int q0 = blockIdx.x * 128;
    int tid  = threadIdx.x;
    int ty   = tid >> 4, tx = tid & 15;     // softmax/S mapping
    int lrow = tid >> 1, half = tid & 1;    // fill mapping
    int rg   = tid >> 3, dg = tid & 7;      // PV mapping: rows rg+32j, dims dg*4..+3

    // Q fill (transposed)
    {
        const float* gq = g_qkv + (size_t)(q0 + lrow)*384 + h*32 + half*16;
        #pragma unroll
        for (int u = 0; u < 4; u++) {
            float4 qv = *(const float4*)(gq + u*4);
            int e = half*16 + u*4;
            Qs[(e+0)*128 + lrow] = qv.x;
            Qs[(e+1)*128 + lrow] = qv.y;
            Qs[(e+2)*128 + lrow] = qv.z;
            Qs[(e+3)*128 + lrow] = qv.w;
        }
    }

    float m[8], l[8];
    u64 o2[4][2];
    #pragma unroll
    for (int r = 0; r < 8; r++) { m[r] = -1e30f; l[r] = 0.f; }
    #pragma unroll
    for (int j = 0; j < 4; j++) { o2[j][0] = 0ULL; o2[j][1] = 0ULL; }

    for (int kv0 = 0; kv0 < BB; kv0 += 128) {
        // K (transposed) + V (row-major) fill
        {
            const float* gk = g_qkv + (size_t)(kv0 + lrow)*384 + 128 + h*32 + half*16;
            const float* gv = g_qkv + (size_t)(kv0 + lrow)*384 + 256 + h*32 + half*16;
            #pragma unroll
            for (int u = 0; u < 4; u++) {
                float4 kvv = *(const float4*)(gk + u*4);
                int e = half*16 + u*4;
                Ks[(e+0)*128 + lrow] = kvv.x;
                Ks[(e+1)*128 + lrow] = kvv.y;
                Ks[(e+2)*128 + lrow] = kvv.z;
                Ks[(e+3)*128 + lrow] = kvv.w;
                float4 vv = *(const float4*)(gv + u*4);
                *(float4*)&Vs[lrow*36 + half*16 + u*4] = vv;
            }
        }
        __syncthreads();

        // S = Q K^T, accumulators column-paired (8 rows x 4 pairs)
        u64 s2[8][4];
        #pragma unroll
        for (int r = 0; r < 8; r++)
            #pragma unroll
            for (int cp = 0; cp < 4; cp++) s2[r][cp] = 0ULL;
        #pragma unroll 4
        for (int e = 0; e < 32; e++) {
            float4 qa = *(const float4*)&Qs[e*128 + ty*8];
            float4 qb = *(const float4*)&Qs[e*128 + ty*8 + 4];
            ulonglong2 ka = *(const ulonglong2*)&Ks[e*128 + tx*8];
            ulonglong2 kb = *(const ulonglong2*)&Ks[e*128 + tx*8 + 4];
            u64 kp[4] = {ka.x, ka.y, kb.x, kb.y};
            float qf[8] = {qa.x, qa.y, qa.z, qa.w, qb.x, qb.y, qb.z, qb.w};
            #pragma unroll
            for (int r = 0; r < 8; r++) {
                u64 qd = dup2(qf[r]);
                #pragma unroll
                for (int cp = 0; cp < 4; cp++) s2[r][cp] = ffma2(qd, kp[cp], s2[r][cp]);
            }
        }

        // online softmax
        #pragma unroll
        for (int r = 0; r < 8; r++) {
            float sv[8];
            #pragma unroll
            for (int cp = 0; cp < 4; cp++) {
                float2 f = unpk(s2[r][cp]);
                sv[2*cp] = f.x * 0.17677669529663688f;
                sv[2*cp+1] = f.y * 0.17677669529663688f;
            }
            float mx = -1e30f;
            #pragma unroll
            for (int c = 0; c < 8; c++) mx = fmaxf(mx, sv[c]);
            #pragma unroll
            for (int off = 8; off > 0; off >>= 1) mx = fmaxf(mx, __shfl_xor_sync(0xffffffffu, mx, off, 16));
            float mi = fmaxf(m[r], mx);
            float alpha = __expf(m[r] - mi);
            float rs = 0.f;
            int row = ty*8 + r;
            #pragma unroll
            for (int cp = 0; cp < 4; cp++) {
                float2 p;
                p.x = __expf(sv[2*cp]   - mi);
                p.y = __expf(sv[2*cp+1] - mi);
                *(float2*)&Ps[row*132 + tx*8 + cp*2] = p;
                rs += p.x + p.y;
            }
            #pragma unroll
            for (int off = 8; off > 0; off >>= 1) rs += __shfl_xor_sync(0xffffffffu, rs, off, 16);
            l[r] = l[r]*alpha + rs;
            m[r] = mi;
            if (tx == 0) Ps[row*132 + 128] = alpha;
        }
        __syncthreads();

        // rescale O by alpha (PV mapping)
        #pragma unroll
        for (int j = 0; j < 4; j++) {
            u64 ad = dup2(Ps[(rg + 32*j)*132 + 128]);
            o2[j][0] = fmul2(o2[j][0], ad);
            o2[j][1] = fmul2(o2[j][1], ad);
        }

        // O += P V
        #pragma unroll 2
        for (int k0 = 0; k0 < 128; k0 += 4) {
            float4 p4[4];
            ulonglong2 vv[4];
            #pragma unroll
            for (int j = 0; j < 4; j++) p4[j] = *(const float4*)&Ps[(rg + 32*j)*132 + k0];
            #pragma unroll
            for (int i = 0; i < 4; i++) vv[i] = *(const ulonglong2*)&Vs[(k0+i)*36 + dg*4];
            #pragma unroll
            for (int j = 0; j < 4; j++) {
                const float* pf = (const float*)&p4[j];
                #pragma unroll
                for (int i = 0; i < 4; i++) {
                    u64 pd = dup2(pf[i]);
                    o2[j][0] = ffma2(pd, vv[i].x, o2[j][0]);
                    o2[j][1] = ffma2(pd, vv[i].y, o2[j][1]);
                }
            }
        }
        __syncthreads();
    }

    // publish l, then final normalize + store (PV mapping)
    #pragma unroll
    for (int r = 0; r < 8; r++)
        if (tx == 0) Ps[(ty*8 + r)*132 + 129] = l[r];
    __syncthreads();

    #pragma unroll
    for (int j = 0; j < 4; j++) {
        int row = rg + 32*j;
        float linv = 1.0f / Ps[row*132 + 129];
        float2 oa = unpk(o2[j][0]);
        float2 ob = unpk(o2[j][1]);
        float4 ov = make_float4(oa.x*linv, oa.y*linv, ob.x*linv, ob.y*linv);
        *(float4*)&g_attn[(size_t)(q0 + row)*128 + h*32 + dg*4] = ov;
    }
}

// ---------------- layernorm (optional class-table add) ----------------
__global__ void k_ln(const float* __restrict__ y, const float* __restrict__ g, const float* __restrict__ bb,
                     const float* __restrict__ catab, const int* __restrict__ labels,
                     float* __restrict__ out) {
    int i = blockIdx.x, d = threadIdx.x;
    float v = y[i*DD + d];
    if (catab) v += catab[labels[i]*DD + d];
    float s = v, s2 = v*v;
    #pragma unroll
    for (int off = 16; off > 0; off >>= 1) {
        s  += __shfl_xor_sync(0xffffffffu, s,  off);
        s2 += __shfl_xor_sync(0xffffffffu, s2, off);
    }
    __shared__ float sm1[4], sm2[4];
    int w = d >> 5, lane = d & 31;
    if (lane == 0) { sm1[w] = s; sm2[w] = s2; }
    __syncthreads();
    s  = sm1[0] + sm1[1] + sm1[2] + sm1[3];
    s2 = sm2[0] + sm2[1] + sm2[2] + sm2[3];
    float mean = s * (1.0f/128.0f);
    float var  = s2 * (1.0f/128.0f) - mean*mean;
    out[i*DD + d] = (v - mean)*rsqrtf(var + 1e-5f)*g[d] + bb[d];
}

// ---------------- per-class cross-attn table ----------------
__global__ void k_ca(const float* __restrict__ emb, const float* __restrict__ wv, const float* __restrict__ bv,
                     const float* __restrict__ wo, const float* __restrict__ bo) {
    __shared__ float e[128], t[128];
    int c = blockIdx.x, j = threadIdx.x;
    e[j] = emb[c*128 + j];
    __syncthreads();
    float s = bv[j];
    #pragma unroll 8
    for (int d0 = 0; d0 < 128; d0++) s += e[d0]*wv[j*128 + d0];
    t[j] = s;
    __syncthreads();
    float s2 = bo[j];
    #pragma unroll 8
    for (int d0 = 0; d0 < 128; d0++) s2 += t[d0]*wo[j*128 + d0];
    g_ca[c*128 + j] = s2;
}

// ---------------- final ----------------
__global__ void k_final(const float* __restrict__ x, const float* __restrict__ w, const float* __restrict__ b,
                        float* __restrict__ out) {
    int gt = blockIdx.x*blockDim.x + threadIdx.x;
    int row = gt >> 5, lane = gt & 31;
    if (row >= BB) return;
    float s = 0.f;
    #pragma unroll
    for (int j = 0; j < 4; j++) s += x[(size_t)row*128 + lane + j*32] * w[lane + j*32];
    #pragma unroll
    for (int off = 16; off > 0; off >>= 1) s += __shfl_xor_sync(0xffffffffu, s, off);
    if (lane == 0) out[row] = 1.0f/(1.0f + expf(-(s + b[0])));
}

// ---------------- launch ----------------
extern "C" void kernel_launch(void* const* d_in, const int* in_sizes, int n_in,
                              void* d_out, int out_size) {
    const float* coords   = (const float*)d_in[0];
    const int*   labels   = (const int*)  d_in[1];
    const float* ce_w     = (const float*)d_in[2];
    const float* ce_b     = (const float*)d_in[3];
    const float* emb      = (const float*)d_in[4];
    const float* sa_in_w  = (const float*)d_in[5];
    const float* sa_in_b  = (const float*)d_in[6];
    const float* sa_out_w = (const float*)d_in[7];
    const float* sa_out_b = (const float*)d_in[8];
    const float* n1_g     = (const float*)d_in[9];
    const float* n1_b     = (const float*)d_in[10];
    const float* m1_w1    = (const float*)d_in[11];
    const float* m1_b1    = (const float*)d_in[12];
    const float* m1_w2    = (const float*)d_in[13];
    const float* m1_b2    = (const float*)d_in[14];
    const float* n2_g     = (const float*)d_in[15];
    const float* n2_b     = (const float*)d_in[16];
    const float* ca_in_w  = (const float*)d_in[17];
    const float* ca_in_b  = (const float*)d_in[18];
    const float* ca_out_w = (const float*)d_in[19];
    const float* ca_out_b = (const float*)d_in[20];
    const float* n3_g     = (const float*)d_in[21];
    const float* n3_b     = (const float*)d_in[22];
    const float* m2_w1    = (const float*)d_in[23];
    const float* m2_b1    = (const float*)d_in[24];
    const float* m2_w2    = (const float*)d_in[25];
    const float* m2_b2    = (const float*)d_in[26];
    const float* n4_g     = (const float*)d_in[27];
    const float* n4_b     = (const float*)d_in[28];
    const float* fin_w    = (const float*)d_in[29];
    const float* fin_b    = (const float*)d_in[30];
    float* out = (float*)d_out;

    float *px, *py, *pqkv, *pattn, *ph, *pca;
    cudaGetSymbolAddress((void**)&px,    g_x);
    cudaGetSymbolAddress((void**)&py,    g_y);
    cudaGetSymbolAddress((void**)&pqkv,  g_qkv);
    cudaGetSymbolAddress((void**)&pattn, g_attn);
    cudaGetSymbolAddress((void**)&ph,    g_h);
    cudaGetSymbolAddress((void**)&pca,   g_ca);

    const int ATTN_SMEM = (32*128 + 32*128 + 128*36 + 128*132) * 4;  // 118784 B
    cudaFuncSetAttribute(k_attn, cudaFuncAttributeMaxDynamicSharedMemorySize, ATTN_SMEM);

    k_embed<<<BB, 128>>>(coords, ce_w, ce_b);
    k_gemm<0><<<dim3(6, 128), 128>>>(px, sa_in_w, sa_in_b, nullptr, pqkv, 384, 128);
    k_attn<<<dim3(32, 4), 256, ATTN_SMEM>>>();
    k_gemm<0><<<dim3(2, 128), 128>>>(pattn, sa_out_w, sa_out_b, px, py, 128, 128);
    k_ln<<<BB, 128>>>(py, n1_g, n1_b, nullptr, nullptr, px);
    k_gemm<1><<<dim3(8, 128), 128>>>(px, m1_w1, m1_b1, nullptr, ph, 512, 128);
    k_gemm<0><<<dim3(2, 128), 128>>>(ph, m1_w2, m1_b2, px, py, 128, 512);
    k_ln<<<BB, 128>>>(py, n2_g, n2_b, nullptr, nullptr, px);
    k_ca<<<10, 128>>>(emb, ca_in_w + 2*DD*DD, ca_in_b + 2*DD, ca_out_w, ca_out_b);
    k_ln<<<BB, 128>>>(px, n3_g, n3_b, pca, labels, py);
    k_gemm<1><<<dim3(8, 128), 128>>>(py, m2_w1, m2_b1, nullptr, ph, 512, 128);
    k_gemm<0><<<dim3(2, 128), 128>>>(ph, m2_w2, m2_b2, py, px, 128, 512);
    k_ln<<<BB, 128>>>(px, n4_g, n4_b, nullptr, nullptr, py);
    k_final<<<512, 256>>>(py, fin_w, fin_b, out);
}

// round 3
// speedup vs baseline: 2.3119x; 2.1159x over previous
#include <cuda_runtime.h>
#include <cuda_bf16.h>
#include <math.h>

#define BB 4096
#define DD 128

typedef unsigned int u32;
typedef unsigned long long u64;

// ---- packed fp32x2 helpers (for the fp32 GEMMs) ----
__device__ __forceinline__ u64 dup2(float a) {
    u64 r; asm("mov.b64 %0,{%1,%1};" : "=l"(r) : "f"(a)); return r;
}
__device__ __forceinline__ u64 ffma2(u64 a, u64 b, u64 c) {
    u64 d; asm("fma.rn.f32x2 %0,%1,%2,%3;" : "=l"(d) : "l"(a), "l"(b), "l"(c)); return d;
}
__device__ __forceinline__ float2 unpk(u64 v) {
    float2 f; asm("mov.b64 {%0,%1},%2;" : "=f"(f.x), "=f"(f.y) : "l"(v)); return f;
}

// ---- tensor-core helpers ----
__device__ __forceinline__ uint4 ldsm4(u32 addr) {
    uint4 r;
    asm volatile("ldmatrix.sync.aligned.m8n8.x4.shared.b16 {%0,%1,%2,%3},[%4];"
        : "=r"(r.x), "=r"(r.y), "=r"(r.z), "=r"(r.w) : "r"(addr));
    return r;
}
__device__ __forceinline__ uint4 ldsm4t(u32 addr) {
    uint4 r;
    asm volatile("ldmatrix.sync.aligned.m8n8.x4.trans.shared.b16 {%0,%1,%2,%3},[%4];"
        : "=r"(r.x), "=r"(r.y), "=r"(r.z), "=r"(r.w) : "r"(addr));
    return r;
}
__device__ __forceinline__ void mma16816(float* c, uint4 a, u32 b0, u32 b1) {
    asm volatile(
        "mma.sync.aligned.m16n8k16.row.col.f32.bf16.bf16.f32 "
        "{%0,%1,%2,%3},{%4,%5,%6,%7},{%8,%9},{%0,%1,%2,%3};"
        : "+f"(c[0]), "+f"(c[1]), "+f"(c[2]), "+f"(c[3])
        : "r"(a.x), "r"(a.y), "r"(a.z), "r"(a.w), "r"(b0), "r"(b1));
}
__device__ __forceinline__ float ex2f(float x) {
    float y; asm("ex2.approx.f32 %0,%1;" : "=f"(y) : "f"(x)); return y;
}
__device__ __forceinline__ u32 cvtbf2(float hi, float lo) {
    u32 r; asm("cvt.rn.bf16x2.f32 %0,%1,%2;" : "=r"(r) : "f"(hi), "f"(lo)); return r;
}
__device__ __forceinline__ u32 s2u(const void* p) {
    return (u32)__cvta_generic_to_shared(p);
}

#define QSCALE 0.17677669529663688f
#define LOG2E  1.4426950408889634f

// ---------------- scratch ----------------
__device__ float g_x[BB*DD];
__device__ float g_y[BB*DD];
__device__ __nv_bfloat16 g_qkvh[BB*3*DD];
__device__ float g_attn[BB*DD];
__device__ float g_h[BB*4*DD];
__device__ float g_ca[10*DD];

// ---------------- embed ----------------
__global__ void k_embed(const float* __restrict__ coords, const float* __restrict__ ce_w,
                        const float* __restrict__ ce_b) {
    int i = blockIdx.x, d = threadIdx.x;
    float c0 = coords[2*i], c1 = coords[2*i+1];
    int j = d >> 1;
    float dv = expf(9.210340371976184f * (float)j * (1.0f/64.0f));
    float pe = (d & 1) ? cosf(c1 / dv) : sinf(c0 / dv);
    g_x[i*DD + d] = c0*ce_w[2*d] + c1*ce_w[2*d+1] + ce_b[d] + pe;
}

// ---------------- GEMM: C = act(A[M,K]@W[N,K]^T + b) (+R) ----------------
// BF16OUT=1: write bf16, scale cols<128 by QSCALE (qkv path only)
template<int ACT, int BF16OUT>
__global__ __launch_bounds__(128) void k_gemm(const float* __restrict__ A, const float* __restrict__ W,
                                              const float* __restrict__ bias, const float* __restrict__ R,
                                              void* __restrict__ Cv, int N, int K) {
    __shared__ float As[2][16][36];
    __shared__ float Ws[2][16][68];
    int tid = threadIdx.x;
    int ty = tid >> 4, tx = tid & 15;
    int m0 = blockIdx.y * 32, n0 = blockIdx.x * 64;
    int ar = tid >> 2, ak = (tid & 3) << 2;
    int wr = tid >> 1, wk = (tid & 1) << 3;
    const float* Ap = A + (size_t)(m0 + ar)*K + ak;
    const float* Wp = W + (size_t)(n0 + wr)*K + wk;
    int nt = K >> 4;

    {
        float4 av = *(const float4*)Ap;
        float4 w0 = *(const float4*)Wp;
        float4 w1 = *(const float4*)(Wp + 4);
        As[0][ak+0][ar]=av.x; As[0][ak+1][ar]=av.y; As[0][ak+2][ar]=av.z; As[0][ak+3][ar]=av.w;
        Ws[0][wk+0][wr]=w0.x; Ws[0][wk+1][wr]=w0.y; Ws[0][wk+2][wr]=w0.z; Ws[0][wk+3][wr]=w0.w;
        Ws[0][wk+4][wr]=w1.x; Ws[0][wk+5][wr]=w1.y; Ws[0][wk+6][wr]=w1.z; Ws[0][wk+7][wr]=w1.w;
    }
    __syncthreads();

    u64 acc[4][2];
    #pragma unroll
    for (int r = 0; r < 4; r++) { acc[r][0] = 0ULL; acc[r][1] = 0ULL; }

    for (int t = 0; t < nt; t++) {
        float4 nav, nw0, nw1;
        if (t + 1 < nt) {
            nav = *(const float4*)(Ap + (t+1)*16);
            nw0 = *(const float4*)(Wp + (t+1)*16);
            nw1 = *(const float4*)(Wp + (t+1)*16 + 4);
        }
        int b = t & 1;
        #pragma unroll
        for (int k = 0; k < 16; k++) {
            float4 a4 = *(const float4*)&As[b][k][ty*4];
            ulonglong2 w2 = *(const ulonglong2*)&Ws[b][k][tx*4];
            u64 d0 = dup2(a4.x), d1 = dup2(a4.y), d2 = dup2(a4.z), d3 = dup2(a4.w);
            acc[0][0] = ffma2(d0, w2.x, acc[0][0]); acc[0][1] = ffma2(d0, w2.y, acc[0][1]);
            acc[1][0] = ffma2(d1, w2.x, acc[1][0]); acc[1][1] = ffma2(d1, w2.y, acc[1][1]);
            acc[2][0] = ffma2(d2, w2.x, acc[2][0]); acc[2][1] = ffma2(d2, w2.y, acc[2][1]);
            acc[3][0] = ffma2(d3, w2.x, acc[3][0]); acc[3][1] = ffma2(d3, w2.y, acc[3][1]);
        }
        if (t + 1 < nt) {
            int nb = b ^ 1;
            As[nb][ak+0][ar]=nav.x; As[nb][ak+1][ar]=nav.y; As[nb][ak+2][ar]=nav.z; As[nb][ak+3][ar]=nav.w;
            Ws[nb][wk+0][wr]=nw0.x; Ws[nb][wk+1][wr]=nw0.y; Ws[nb][wk+2][wr]=nw0.z; Ws[nb][wk+3][wr]=nw0.w;
            Ws[nb][wk+4][wr]=nw1.x; Ws[nb][wk+5][wr]=nw1.y; Ws[nb][wk+6][wr]=nw1.z; Ws[nb][wk+7][wr]=nw1.w;
        }
        __syncthreads();
    }

    #pragma unroll
    for (int r = 0; r < 4; r++) {
        int row = m0 + ty*4 + r;
        float2 f0 = unpk(acc[r][0]);
        float2 f1 = unpk(acc[r][1]);
        float vals[4] = {f0.x, f0.y, f1.x, f1.y};
        #pragma unroll
        for (int c = 0; c < 4; c++) {
            float val = vals[c] + bias[n0 + tx*4 + c];
            if (ACT == 1) val = 0.5f*val*(1.0f + erff(val*0.7071067811865475f));
            vals[c] = val;
        }
        if (BF16OUT) {
            __nv_bfloat16* C = (__nv_bfloat16*)Cv;
            float sc = (n0 + tx*4 < 128) ? QSCALE : 1.0f;  // whole float4 is in one region (q cols 0..127)
            u32 p0 = cvtbf2(vals[1]*sc, vals[0]*sc);
            u32 p1 = cvtbf2(vals[3]*sc, vals[2]*sc);
            uint2 pk = make_uint2(p0, p1);
            *(uint2*)(C + (size_t)row*N + n0 + tx*4) = pk;
        } else {
            float* C = (float*)Cv;
            float4 v = make_float4(vals[0], vals[1], vals[2], vals[3]);
            if (R) {
                float4 rv = *(const float4*)(R + (size_t)row*N + n0 + tx*4);
                v.x += rv.x; v.y += rv.y; v.z += rv.z; v.w += rv.w;
            }
            *(float4*)(C + (size_t)row*N + n0 + tx*4) = v;
        }
    }
}

// ---------------- flash attention, bf16 mma.sync: 1 CTA = 128 q x 1 head ----------------
// smem bf16: Qs[128][40], Ks[2][128][40], Vs[2][128][40]  (51200 B)
__global__ __launch_bounds__(256, 1) void k_attn() {
    extern __shared__ __nv_bfloat16 smh[];
    __nv_bfloat16* Qs  = smh;            // 5120 elems
    __nv_bfloat16* Ks0 = smh + 5120;
    __nv_bfloat16* Ks1 = smh + 10240;
    __nv_bfloat16* Vs0 = smh + 15360;
    __nv_bfloat16* Vs1 = smh + 20480;

    const int h  = blockIdx.y;
    const int q0 = blockIdx.x * 128;
    const int tid  = threadIdx.x;
    const int lane = tid & 31;
    const int w    = tid >> 5;

    const __nv_bfloat16* QKV = g_qkvh;

    // ---- prologue: stage Q tile and KV tile 0 ----
    const int lr = tid >> 1, lh = tid & 1;      // row, 16-elem half
    {
        const uint4* gq = (const uint4*)(QKV + (size_t)(q0 + lr)*384 + h*32 + lh*16);
        uint4 a = gq[0], b = gq[1];
        *(uint4*)(Qs + lr*40 + lh*16)     = a;
        *(uint4*)(Qs + lr*40 + lh*16 + 8) = b;
        const uint4* gk = (const uint4*)(QKV + (size_t)lr*384 + 128 + h*32 + lh*16);
        uint4 ka = gk[0], kb = gk[1];
        *(uint4*)(Ks0 + lr*40 + lh*16)     = ka;
        *(uint4*)(Ks0 + lr*40 + lh*16 + 8) = kb;
        const uint4* gv = (const uint4*)(QKV + (size_t)lr*384 + 256 + h*32 + lh*16);
        uint4 va = gv[0], vb = gv[1];
        *(uint4*)(Vs0 + lr*40 + lh*16)     = va;
        *(uint4*)(Vs0 + lr*40 + lh*16 + 8) = vb;
    }
    __syncthreads();

    // ---- per-lane ldmatrix base offsets (bytes within a 128x40 tile) ----
    const u32 frag_off = (u32)((lane & 15)*80 + (lane >> 4)*16);
    const u32 aQ  = s2u(Qs)  + (u32)(w*16*80) + frag_off;
    const u32 aK0 = s2u(Ks0) + frag_off;
    const u32 aK1 = s2u(Ks1) + frag_off;
    const u32 aV0 = s2u(Vs0) + frag_off;
    const u32 aV1 = s2u(Vs1) + frag_off;

    uint4 qa0 = ldsm4(aQ);        // k-chunk 0 (hd 0..15)
    uint4 qa1 = ldsm4(aQ + 32);   // k-chunk 1 (hd 16..31)

    float o[4][4];
    #pragma unroll
    for (int j = 0; j < 4; j++)
        #pragma unroll
        for (int c = 0; c < 4; c++) o[j][c] = 0.f;
    float m0 = -1e30f, m1 = -1e30f, l0 = 0.f, l1 = 0.f;

    for (int t = 0; t < 32; t++) {
        // prefetch next KV tile into regs
        uint4 ka, kb, va, vb;
        if (t < 31) {
            int kvr = (t+1)*128 + lr;
            const uint4* gk = (const uint4*)(QKV + (size_t)kvr*384 + 128 + h*32 + lh*16);
            ka = gk[0]; kb = gk[1];
            const uint4* gv = (const uint4*)(QKV + (size_t)kvr*384 + 256 + h*32 + lh*16);
            va = gv[0]; vb = gv[1];
        }
        const u32 aK = (t & 1) ? aK1 : aK0;
        const u32 aV = (t & 1) ? aV1 : aV0;

        // ---- S = Q K^T : c[16 ntiles][4] ----
        float c[16][4];
        #pragma unroll
        for (int j = 0; j < 16; j++) { c[j][0]=0.f; c[j][1]=0.f; c[j][2]=0.f; c[j][3]=0.f; }
        #pragma unroll
        for (int g = 0; g < 8; g++) {
            uint4 k0 = ldsm4(aK + g*1280);
            uint4 k1 = ldsm4(aK + g*1280 + 32);
            mma16816(c[2*g],   qa0, k0.x, k0.z);
            mma16816(c[2*g],   qa1, k1.x, k1.z);
            mma16816(c[2*g+1], qa0, k0.y, k0.w);
            mma16816(c[2*g+1], qa1, k1.y, k1.w);
        }

        // ---- online softmax (rows lane/4 and lane/4+8) ----
        float mx0 = -1e30f, mx1 = -1e30f;
        #pragma unroll
        for (int j = 0; j < 16; j++) {
            mx0 = fmaxf(mx0, fmaxf(c[j][0], c[j][1]));
            mx1 = fmaxf(mx1, fmaxf(c[j][2], c[j][3]));
        }
        mx0 = fmaxf(mx0, __shfl_xor_sync(0xffffffffu, mx0, 1));
        mx0 = fmaxf(mx0, __shfl_xor_sync(0xffffffffu, mx0, 2));
        mx1 = fmaxf(mx1, __shfl_xor_sync(0xffffffffu, mx1, 1));
        mx1 = fmaxf(mx1, __shfl_xor_sync(0xffffffffu, mx1, 2));
        float mi0 = fmaxf(m0, mx0), mi1 = fmaxf(m1, mx1);
        float al0 = ex2f((m0 - mi0)*LOG2E);
        float al1 = ex2f((m1 - mi1)*LOG2E);
        float tm0 = mi0*LOG2E, tm1 = mi1*LOG2E;
        float rs0 = 0.f, rs1 = 0.f;
        #pragma unroll
        for (int j = 0; j < 16; j++) {
            c[j][0] = ex2f(fmaf(c[j][0], LOG2E, -tm0));
            c[j][1] = ex2f(fmaf(c[j][1], LOG2E, -tm0));
            c[j][2] = ex2f(fmaf(c[j][2], LOG2E, -tm1));
            c[j][3] = ex2f(fmaf(c[j][3], LOG2E, -tm1));
            rs0 += c[j][0] + c[j][1];
            rs1 += c[j][2] + c[j][3];
        }
        rs0 += __shfl_xor_sync(0xffffffffu, rs0, 1);
        rs0 += __shfl_xor_sync(0xffffffffu, rs0, 2);
        rs1 += __shfl_xor_sync(0xffffffffu, rs1, 1);
        rs1 += __shfl_xor_sync(0xffffffffu, rs1, 2);
        l0 = l0*al0 + rs0; m0 = mi0;
        l1 = l1*al1 + rs1; m1 = mi1;

        // rescale O
        #pragma unroll
        for (int j = 0; j < 4; j++) {
            o[j][0] *= al0; o[j][1] *= al0;
            o[j][2] *= al1; o[j][3] *= al1;
        }

        // ---- O += P V ----
        #pragma unroll
        for (int kc = 0; kc < 8; kc++) {
            uint4 pa;
            pa.x = cvtbf2(c[2*kc][1],   c[2*kc][0]);
            pa.y = cvtbf2(c[2*kc][3],   c[2*kc][2]);
            pa.z = cvtbf2(c[2*kc+1][1], c[2*kc+1][0]);
            pa.w = cvtbf2(c[2*kc+1][3], c[2*kc+1][2]);
            uint4 v0 = ldsm4t(aV + kc*1280);
            uint4 v1 = ldsm4t(aV + kc*1280 + 32);
            mma16816(o[0], pa, v0.x, v0.y);
            mma16816(o[1], pa, v0.z, v0.w);
            mma16816(o[2], pa, v1.x, v1.y);
            mma16816(o[3], pa, v1.z, v1.w);
        }

        // stage next tile
        if (t < 31) {
            __nv_bfloat16* Kd = (t & 1) ? Ks0 : Ks1;
            __nv_bfloat16* Vd = (t & 1) ? Vs0 : Vs1;
            *(uint4*)(Kd + lr*40 + lh*16)     = ka;
            *(uint4*)(Kd + lr*40 + lh*16 + 8) = kb;
            *(uint4*)(Vd + lr*40 + lh*16)     = va;
            *(uint4*)(Vd + lr*40 + lh*16 + 8) = vb;
        }
        __syncthreads();
    }

    // ---- write O ----
    float li0 = 1.0f / l0, li1 = 1.0f / l1;
    int row0 = q0 + w*16 + (lane >> 2);
    int col  = h*32 + (lane & 3)*2;
    #pragma unroll
    for (int j = 0; j < 4; j++) {
        *(float2*)&g_attn[(size_t)row0*128 + col + j*8]     = make_float2(o[j][0]*li0, o[j][1]*li0);
        *(float2*)&g_attn[(size_t)(row0+8)*128 + col + j*8] = make_float2(o[j][2]*li1, o[j][3]*li1);
    }
}

// ---------------- layernorm (optional class-table add) ----------------
__global__ void k_ln(const float* __restrict__ y, const float* __restrict__ g, const float* __restrict__ bb,
                     const float* __restrict__ catab, const int* __restrict__ labels,
                     float* __restrict__ out) {
    int i = blockIdx.x, d = threadIdx.x;
    float v = y[i*DD + d];
    if (catab) v += catab[labels[i]*DD + d];
    float s = v, s2 = v*v;
    #pragma unroll
    for (int off = 16; off > 0; off >>= 1) {
        s  += __shfl_xor_sync(0xffffffffu, s,  off);
        s2 += __shfl_xor_sync(0xffffffffu, s2, off);
    }
    __shared__ float sm1[4], sm2[4];
    int w = d >> 5, lane = d & 31;
    if (lane == 0) { sm1[w] = s; sm2[w] = s2; }
    __syncthreads();
    s  = sm1[0] + sm1[1] + sm1[2] + sm1[3];
    s2 = sm2[0] + sm2[1] + sm2[2] + sm2[3];
    float mean = s * (1.0f/128.0f);
    float var  = s2 * (1.0f/128.0f) - mean*mean;
    out[i*DD + d] = (v - mean)*rsqrtf(var + 1e-5f)*g[d] + bb[d];
}

// ---------------- per-class cross-attn table ----------------
__global__ void k_ca(const float* __restrict__ emb, const float* __restrict__ wv, const float* __restrict__ bv,
                     const float* __restrict__ wo, const float* __restrict__ bo) {
    __shared__ float e[128], t[128];
    int c = blockIdx.x, j = threadIdx.x;
    e[j] = emb[c*128 + j];
    __syncthreads();
    float s = bv[j];
    #pragma unroll 8
    for (int d0 = 0; d0 < 128; d0++) s += e[d0]*wv[j*128 + d0];
    t[j] = s;
    __syncthreads();
    float s2 = bo[j];
    #pragma unroll 8
    for (int d0 = 0; d0 < 128; d0++) s2 += t[d0]*wo[j*128 + d0];
    g_ca[c*128 + j] = s2;
}

// ---------------- final ----------------
__global__ void k_final(const float* __restrict__ x, const float* __restrict__ w, const float* __restrict__ b,
                        float* __restrict__ out) {
    int gt = blockIdx.x*blockDim.x + threadIdx.x;
    int row = gt >> 5, lane = gt & 31;
    if (row >= BB) return;
    float s = 0.f;
    #pragma unroll
    for (int j = 0; j < 4; j++) s += x[(size_t)row*128 + lane + j*32] * w[lane + j*32];
    #pragma unroll
    for (int off = 16; off > 0; off >>= 1) s += __shfl_xor_sync(0xffffffffu, s, off);
    if (lane == 0) out[row] = 1.0f/(1.0f + expf(-(s + b[0])));
}

// ---------------- launch ----------------
extern "C" void kernel_launch(void* const* d_in, const int* in_sizes, int n_in,
                              void* d_out, int out_size) {
    const float* coords   = (const float*)d_in[0];
    const int*   labels   = (const int*)  d_in[1];
    const float* ce_w     = (const float*)d_in[2];
    const float* ce_b     = (const float*)d_in[3];
    const float* emb      = (const float*)d_in[4];
    const float* sa_in_w  = (const float*)d_in[5];
    const float* sa_in_b  = (const float*)d_in[6];
    const float* sa_out_w = (const float*)d_in[7];
    const float* sa_out_b = (const float*)d_in[8];
    const float* n1_g     = (const float*)d_in[9];
    const float* n1_b     = (const float*)d_in[10];
    const float* m1_w1    = (const float*)d_in[11];
    const float* m1_b1    = (const float*)d_in[12];
    const float* m1_w2    = (const float*)d_in[13];
    const float* m1_b2    = (const float*)d_in[14];
    const float* n2_g     = (const float*)d_in[15];
    const float* n2_b     = (const float*)d_in[16];
    const float* ca_in_w  = (const float*)d_in[17];
    const float* ca_in_b  = (const float*)d_in[18];
    const float* ca_out_w = (const float*)d_in[19];
    const float* ca_out_b = (const float*)d_in[20];
    const float* n3_g     = (const float*)d_in[21];
    const float* n3_b     = (const float*)d_in[22];
    const float* m2_w1    = (const float*)d_in[23];
    const float* m2_b1    = (const float*)d_in[24];
    const float* m2_w2    = (const float*)d_in[25];
    const float* m2_b2    = (const float*)d_in[26];
    const float* n4_g     = (const float*)d_in[27];
    const float* n4_b     = (const float*)d_in[28];
    const float* fin_w    = (const float*)d_in[29];
    const float* fin_b    = (const float*)d_in[30];
    float* out = (float*)d_out;

    float *px, *py, *pattn, *ph, *pca;
    __nv_bfloat16* pqkvh;
    cudaGetSymbolAddress((void**)&px,    g_x);
    cudaGetSymbolAddress((void**)&py,    g_y);
    cudaGetSymbolAddress((void**)&pqkvh, g_qkvh);
    cudaGetSymbolAddress((void**)&pattn, g_attn);
    cudaGetSymbolAddress((void**)&ph,    g_h);
    cudaGetSymbolAddress((void**)&pca,   g_ca);

    const int ATTN_SMEM = 5 * 128 * 40 * 2;  // 51200 B
    cudaFuncSetAttribute(k_attn, cudaFuncAttributeMaxDynamicSharedMemorySize, ATTN_SMEM);

    k_embed<<<BB, 128>>>(coords, ce_w, ce_b);
    k_gemm<0,1><<<dim3(6, 128), 128>>>(px, sa_in_w, sa_in_b, nullptr, pqkvh, 384, 128);
    k_attn<<<dim3(32, 4), 256, ATTN_SMEM>>>();
    k_gemm<0,0><<<dim3(2, 128), 128>>>(pattn, sa_out_w, sa_out_b, px, py, 128, 128);
    k_ln<<<BB, 128>>>(py, n1_g, n1_b, nullptr, nullptr, px);
    k_gemm<1,0><<<dim3(8, 128), 128>>>(px, m1_w1, m1_b1, nullptr, ph, 512, 128);
    k_gemm<0,0><<<dim3(2, 128), 128>>>(ph, m1_w2, m1_b2, px, py, 128, 512);
    k_ln<<<BB, 128>>>(py, n2_g, n2_b, nullptr, nullptr, px);
    k_ca<<<10, 128>>>(emb, ca_in_w + 2*DD*DD, ca_in_b + 2*DD, ca_out_w, ca_out_b);
    k_ln<<<BB, 128>>>(px, n3_g, n3_b, pca, labels, py);
    k_gemm<1,0><<<dim3(8, 128), 128>>>(py, m2_w1, m2_b1, nullptr, ph, 512, 128);
    k_gemm<0,0><<<dim3(2, 128), 128>>>(ph, m2_w2, m2_b2, py, px, 128, 512);
    k_ln<<<BB, 128>>>(px, n4_g, n4_b, nullptr, nullptr, py);
    k_final<<<512, 256>>>(py, fin_w, fin_b, out);
}